// round 17
// baseline (speedup 1.0000x reference)
#include <cuda_runtime.h>

// GADBase guided anisotropic diffusion — persistent kernel v6c.
// Tile 128 cols x 32 rows, 256 threads (8 warps), thread = 2 cols x 8 rows.
// Image v[8] (float2) + left-cond cl[8] in registers (24 regs -> 64-reg cap,
// 4 CTAs/SM, 32 warps/SM). Other conductances in SMEM. Warp = 64x8 = half a
// block row -> in-warp ratio reduction (2 shfl). 1 syncthreads/iter; mid-tile
// col seam via parity SMEM buffer; inter-CTA halo via global rings +
// acquire/release flags with nanosleep backoff.

#define NPIX   (1024*1024)
#define CV_OFF 2097152
#define CH_OFF 4192256
#define GX  8
#define GYT 32
#define NCTA (2*GX*GYT)        // 512

// dynamic SMEM layout (floats)
#define OFF_A    0             // 33*128 = 4224 : 0.24*cv, boundary k above row k
#define OFF_C    4224          // 32*132 = 4224 : 0.24*ch, idx3 = west pad, 4.. cols
#define OFF_BT   8448          // [2][4][2][128] = 2048 : parity inter-warp rows
#define OFF_SEAM 10496         // [2][2][32] = 128 : parity col-63/64 seam
#define OFF_SRC  10624         // 64
#define OFF_MSK  10688         // 64
#define SMEMF    10752         // 43008 bytes -> 4 CTAs/SM (172 KB)

__device__ float g_shift;
__device__ int   g_flag[NCTA];
__device__ float g_brow[2][2][GYT][2][1024];   // [parity][batch][tyr][top/bot][col]
__device__ float g_bcol[2][2][GX][2][1024];    // [parity][batch][bx][left/right][row]

// ---------------------------------------------------------------------------
__global__ void k_pre(const float* __restrict__ src)
{
    __shared__ float red[32];
    int tid = threadIdx.x;                       // 1024 threads
    float mn = 1e30f;
    for (int i = tid; i < 2*128*128; i += 1024) mn = fminf(mn, src[i]);
    #pragma unroll
    for (int o = 16; o; o >>= 1) mn = fminf(mn, __shfl_xor_sync(~0u, mn, o));
    if ((tid & 31) == 0) red[tid >> 5] = mn;
    __syncthreads();
    if (tid < 32) {
        float v = red[tid];
        #pragma unroll
        for (int o = 16; o; o >>= 1) v = fminf(v, __shfl_xor_sync(~0u, v, o));
        if (tid == 0) g_shift = (v <= 0.1f) ? 0.1f : 0.0f;
    }
    if (tid < NCTA) g_flag[tid] = -1;
}

// ---------------------------------------------------------------------------
__device__ __forceinline__ void spin_ge(const int* p, int t)
{
    int v;
    asm volatile("ld.acquire.gpu.global.s32 %0, [%1];"
                 : "=r"(v) : "l"(p) : "memory");
    while (v < t) {
        __nanosleep(32);
        asm volatile("ld.acquire.gpu.global.s32 %0, [%1];"
                     : "=r"(v) : "l"(p) : "memory");
    }
}

__device__ __forceinline__ void flag_release(int* p, int val)
{
    int old;
    asm volatile("atom.release.gpu.global.exch.b32 %0, [%1], %2;"
                 : "=r"(old) : "l"(p), "r"(val) : "memory");
}

extern __shared__ float sm[];

// ---------------------------------------------------------------------------
__global__ void __launch_bounds__(256, 4)
k_diffuse(const float* __restrict__ guide, const float* __restrict__ y,
          const float* __restrict__ src,   const float* __restrict__ mask,
          float* __restrict__ out)
{
    const int tid  = threadIdx.x;
    const int w    = tid >> 5, lane = tid & 31;
    const int wr   = w >> 1, wc = w & 1;             // warp-row 0..3, warp-col 0..1
    const int bx = blockIdx.x, tyr = blockIdx.y, b = blockIdx.z;
    const int colbase = bx*128, rowbase = tyr*32;
    const int c0 = wc*64 + lane*2, r0 = wr*8;        // tile-local
    const int gc0 = colbase + c0, gr0 = rowbase + r0;
    const int cid = (b*GYT + tyr)*GX + bx;
    const float shift = g_shift;
    const float K2 = 0.03f*0.03f;

    float2 v[8];

    // ======================= prologue ======================================
    const float* G0 = guide + b*3*NPIX;
    const float* G1 = G0 + NPIX;
    const float* G2 = G1 + NPIX;
    const float* Yp = y + b*NPIX;

    float2 p0 = {0,0}, p1 = {0,0}, p2 = {0,0}, py = {0,0};
    #pragma unroll
    for (int j = 0; j < 10; j++) {
        int row = gr0 - 1 + j;
        bool inr = (unsigned)row < 1024u;
        int off = row*1024 + gc0;
        float2 q0 = {0,0}, q1 = {0,0}, q2 = {0,0}, qy = {0,0};
        if (inr) {
            q0 = *(const float2*)(G0 + off);
            q1 = *(const float2*)(G1 + off);
            q2 = *(const float2*)(G2 + off);
            qy = *(const float2*)(Yp + off);
        }
        if (j >= 1) {
            int brow = row - 1;                      // boundary (brow, brow+1)
            float2 av = {0,0};
            if ((unsigned)brow < 1023u) {
                float sx = 0.25f*(fabsf(q0.x-p0.x)+fabsf(q1.x-p1.x)+fabsf(q2.x-p2.x)+fabsf(qy.x-py.x));
                float sy = 0.25f*(fabsf(q0.y-p0.y)+fabsf(q1.y-p1.y)+fabsf(q2.y-p2.y)+fabsf(qy.y-py.y));
                float2 cv2 = make_float2(1.f/(1.f + sx*sx/K2), 1.f/(1.f + sy*sy/K2));
                if (j >= 2)                          // ownership: brow in [gr0, gr0+7]
                    *(float2*)(out + CV_OFF + b*(1023*1024) + brow*1024 + gc0) = cv2;
                av = make_float2(0.24f*cv2.x, 0.24f*cv2.y);
            }
            *(float2*)&sm[OFF_A + (r0 + j - 1)*128 + c0] = av;
        }
        if (j >= 1 && j <= 8) {
            int i = j - 1;                           // local row r0+i
            v[i] = make_float2(qy.x + shift, qy.y + shift);
            float r0s = 0.f, r1s = 0.f, r2s = 0.f, rys = 0.f;
            if (gc0 + 2 < 1024) {
                r0s = G0[off+2]; r1s = G1[off+2]; r2s = G2[off+2]; rys = Yp[off+2];
            }
            float sx = 0.25f*(fabsf(q0.y-q0.x)+fabsf(q1.y-q1.x)+fabsf(q2.y-q2.x)+fabsf(qy.y-qy.x));
            float sy = 0.25f*(fabsf(r0s-q0.y)+fabsf(r1s-q1.y)+fabsf(r2s-q2.y)+fabsf(rys-qy.y));
            float chx = 1.f/(1.f + sx*sx/K2);
            float chy = (gc0 + 1 < 1023) ? 1.f/(1.f + sy*sy/K2) : 0.f;
            float* cho = out + CH_OFF + b*(1024*1023) + row*1023 + gc0;
            cho[0] = chx;
            if (gc0 + 1 < 1023) cho[1] = chy;
            *(float2*)&sm[OFF_C + (r0+i)*132 + 4 + c0] =
                make_float2(0.24f*chx, 0.24f*chy);
            if (lane == 0 && wc == 0) {              // west pad
                float westch = 0.f;
                if (bx > 0) {
                    float l0 = G0[off-1], l1 = G1[off-1], l2 = G2[off-1], ly = Yp[off-1];
                    float s = 0.25f*(fabsf(q0.x-l0)+fabsf(q1.x-l1)+fabsf(q2.x-l2)+fabsf(qy.x-ly));
                    westch = 0.24f/(1.f + s*s/K2);
                }
                sm[OFF_C + (r0+i)*132 + 3] = westch;
            }
        }
        p0 = q0; p1 = q1; p2 = q2; py = qy;
    }

    if (tid < 64) {                                  // 4 block-rows x 16 block-cols
        int br = tid >> 4, bc = tid & 15;
        int bi = b*16384 + ((rowbase>>3) + br)*128 + (colbase>>3) + bc;
        sm[OFF_SRC + tid] = src[bi] + shift;
        sm[OFF_MSK + tid] = (mask[bi] < 0.5f) ? 0.f : 1.f;
    }

    const bool hw = (bx > 0), he = (bx < GX-1);

    // state-0 boundary publishes (parity 0)
    *(float2*)&sm[OFF_BT + ((0*4 + wr)*2 + 0)*128 + c0] = v[0];
    *(float2*)&sm[OFF_BT + ((0*4 + wr)*2 + 1)*128 + c0] = v[7];
    if (wr == 0 && tyr > 0)     *(float2*)&g_brow[0][b][tyr][0][gc0] = v[0];
    if (wr == 3 && tyr < GYT-1) *(float2*)&g_brow[0][b][tyr][1][gc0] = v[7];
    if (lane == 0 && wc == 0 && hw) {
        float* d = &g_bcol[0][b][bx][0][rowbase + r0];
        *(float4*)d       = make_float4(v[0].x, v[1].x, v[2].x, v[3].x);
        *(float4*)(d + 4) = make_float4(v[4].x, v[5].x, v[6].x, v[7].x);
    }
    if (lane == 31 && wc == 1 && he) {
        float* d = &g_bcol[0][b][bx][1][rowbase + r0];
        *(float4*)d       = make_float4(v[0].y, v[1].y, v[2].y, v[3].y);
        *(float4*)(d + 4) = make_float4(v[4].y, v[5].y, v[6].y, v[7].y);
    }
    if (lane == 31 && wc == 0) {                     // col 63 -> seam side 1
        #pragma unroll
        for (int i = 0; i < 8; i++) sm[OFF_SEAM + 0*64 + 32 + r0 + i] = v[i].y;
    }
    if (lane == 0 && wc == 1) {                      // col 64 -> seam side 0
        #pragma unroll
        for (int i = 0; i < 8; i++) sm[OFF_SEAM + 0*64 + r0 + i] = v[i].x;
    }
    __syncthreads();
    if (tid == 0) flag_release(&g_flag[cid], 0);

    // iteration-invariant left horizontal conductance -> registers
    float cl[8];
    #pragma unroll
    for (int i = 0; i < 8; i++) cl[i] = sm[OFF_C + (r0+i)*132 + 3 + c0];

    const int bsel = wr*16 + wc*8 + (lane >> 2);
    const float b_src = sm[OFF_SRC + bsel];
    const float b_msk = sm[OFF_MSK + bsel];

    // ======================= 64 diffusion iterations =======================
    for (int t = 0; t < 64; t++) {
        int par = t & 1, pn = par ^ 1;

        // vertical halo rows
        float2 up;
        if (wr == 0) {
            if (tyr > 0) { spin_ge(&g_flag[cid - GX], t);
                           up = __ldcg((const float2*)&g_brow[par][b][tyr-1][1][gc0]); }
            else up = make_float2(0,0);
        } else up = *(const float2*)&sm[OFF_BT + ((par*4 + wr - 1)*2 + 1)*128 + c0];
        float2 dn;
        if (wr == 3) {
            if (tyr < GYT-1) { spin_ge(&g_flag[cid + GX], t);
                               dn = __ldcg((const float2*)&g_brow[par][b][tyr+1][0][gc0]); }
            else dn = make_float2(0,0);
        } else dn = *(const float2*)&sm[OFF_BT + ((par*4 + wr + 1)*2 + 0)*128 + c0];

        // edge flag spins (reader lanes only)
        if (lane == 0  && wc == 0 && hw) spin_ge(&g_flag[cid - 1], t);
        if (lane == 31 && wc == 1 && he) spin_ge(&g_flag[cid + 1], t);
        const float* wring = &g_bcol[par][b][hw ? bx-1 : 0][1][rowbase + r0];
        const float* ering = &g_bcol[par][b][he ? bx+1 : 0][0][rowbase + r0];

        // stencil (register chain down the 8 rows)
        float2 pv = up;
        float2 a0 = *(const float2*)&sm[OFF_A + r0*128 + c0];
        float acc = 0.f;
        #pragma unroll
        for (int i = 0; i < 8; i++) {
            float2 cur = v[i];
            float2 nxt = (i < 7) ? v[i+1] : dn;
            float2 a1 = *(const float2*)&sm[OFF_A + (r0+i+1)*128 + c0];
            float2 c  = *(const float2*)&sm[OFF_C + (r0+i)*132 + 4 + c0];
            float lf = __shfl_up_sync(~0u, cur.y, 1);
            if (lane == 0)
                lf = (wc == 0) ? (hw ? __ldcg(wring + i) : 0.f)
                               : sm[OFF_SEAM + par*64 + 32 + r0 + i];   // col 63
            float rt = __shfl_down_sync(~0u, cur.x, 1);
            if (lane == 31)
                rt = (wc == 1) ? (he ? __ldcg(ering + i) : 0.f)
                               : sm[OFF_SEAM + par*64 + r0 + i];        // col 64
            float nx = cur.x + (a1.x*(nxt.x-cur.x) - a0.x*(cur.x-pv.x)
                              + c.x*(cur.y-cur.x)  - cl[i]*(cur.x-lf));
            float ny = cur.y + (a1.y*(nxt.y-cur.y) - a0.y*(cur.y-pv.y)
                              + c.y*(rt - cur.y)   - c.x*(cur.y-cur.x));
            v[i] = make_float2(nx, ny);
            acc += nx + ny;
            pv = cur; a0 = a1;
        }

        // 8x8 block sum: block = 4 adjacent lanes (8 cols) x 8 in-thread rows
        float bsum = acc;
        bsum += __shfl_xor_sync(~0u, bsum, 1);
        bsum += __shfl_xor_sync(~0u, bsum, 2);
        float ratio = (b_msk != 0.f)
                    ? __fdividef(b_src, bsum*(1.f/64.f) + 1e-8f) : 1.f;
        #pragma unroll
        for (int i = 0; i < 8; i++) { v[i].x *= ratio; v[i].y *= ratio; }

        if (t == 63) break;

        // publish state t+1 boundaries
        *(float2*)&sm[OFF_BT + ((pn*4 + wr)*2 + 0)*128 + c0] = v[0];
        *(float2*)&sm[OFF_BT + ((pn*4 + wr)*2 + 1)*128 + c0] = v[7];
        if (wr == 0 && tyr > 0)     __stcg((float2*)&g_brow[pn][b][tyr][0][gc0], v[0]);
        if (wr == 3 && tyr < GYT-1) __stcg((float2*)&g_brow[pn][b][tyr][1][gc0], v[7]);
        if (lane == 0 && wc == 0 && hw) {
            float* d = &g_bcol[pn][b][bx][0][rowbase + r0];
            __stcg((float4*)d,       make_float4(v[0].x, v[1].x, v[2].x, v[3].x));
            __stcg((float4*)(d + 4), make_float4(v[4].x, v[5].x, v[6].x, v[7].x));
        }
        if (lane == 31 && wc == 1 && he) {
            float* d = &g_bcol[pn][b][bx][1][rowbase + r0];
            __stcg((float4*)d,       make_float4(v[0].y, v[1].y, v[2].y, v[3].y));
            __stcg((float4*)(d + 4), make_float4(v[4].y, v[5].y, v[6].y, v[7].y));
        }
        if (lane == 31 && wc == 0) {
            #pragma unroll
            for (int i = 0; i < 8; i++) sm[OFF_SEAM + pn*64 + 32 + r0 + i] = v[i].y;
        }
        if (lane == 0 && wc == 1) {
            #pragma unroll
            for (int i = 0; i < 8; i++) sm[OFF_SEAM + pn*64 + r0 + i] = v[i].x;
        }
        __syncthreads();               // CTA publishes done (cumulative for release)
        if (tid == 0) flag_release(&g_flag[cid], t + 1);
    }

    // ======================= epilogue ======================================
    #pragma unroll
    for (int i = 0; i < 8; i++) {
        float2 o = make_float2(v[i].x - shift, v[i].y - shift);
        *(float2*)(out + b*NPIX + (gr0 + i)*1024 + gc0) = o;
    }
}

// ---------------------------------------------------------------------------
extern "C" void kernel_launch(void* const* d_in, const int* in_sizes, int n_in,
                              void* d_out, int out_size)
{
    const float* guide = (const float*)d_in[0];
    const float* y     = (const float*)d_in[1];
    const float* src   = (const float*)d_in[2];
    const float* mask  = (const float*)d_in[3];
    float* out = (float*)d_out;

    cudaFuncSetAttribute(k_diffuse, cudaFuncAttributeMaxDynamicSharedMemorySize,
                         SMEMF * sizeof(float));

    k_pre<<<1, 1024>>>(src);
    dim3 g(GX, GYT, 2);                 // 512 CTAs — 4/SM, all co-resident
    k_diffuse<<<g, 256, SMEMF * sizeof(float)>>>(guide, y, src, mask, out);
}